// round 16
// baseline (speedup 1.0000x reference)
#include <cuda_runtime.h>
#include <cuda_bf16.h>
#include <cstdint>
#include <float.h>

#define W 128
#define BINS 50
#define MPAD 52              // row stride (divisible by 4 for float4 zeroing)
#define THREADS 256
#define NWARP (THREADS / 32)
#define FULL 0xFFFFFFFFu

// Order-preserving float->uint map: monotone for all finite floats.
__device__ __forceinline__ unsigned fkey(float f) {
    unsigned b = __float_as_uint(f);
    return b ^ (((int)b >> 31) | 0x80000000u);
}
__device__ __forceinline__ float funkey(unsigned k) {
    unsigned b = k ^ ((~(int)k >> 31) | 0x80000000u);
    return __uint_as_float(b);
}

__global__ __launch_bounds__(THREADS, 8)
void mtf_kernel(const float* __restrict__ X, float* __restrict__ out, int S) {
    __shared__ __align__(16) int bins[W];
    __shared__ __align__(16) float mtm[BINS * MPAD];
    __shared__ unsigned smn[NWARP], smx[NWARP];

    const int s    = blockIdx.x;
    const int tid  = threadIdx.x;
    const int lane = tid & 31;
    const int wid  = tid >> 5;

    const float* x = X + (size_t)s * W;

    // Zero transition counts (vectorized STS.128).
    for (int i = tid; i < BINS * MPAD / 4; i += THREADS) {
        reinterpret_cast<float4*>(mtm)[i] = make_float4(0.f, 0.f, 0.f, 0.f);
    }

    // Load series value (threads 0..127); per-warp min/max via redux on keys.
    float v = 0.0f;
    if (tid < W) v = x[tid];
    unsigned key = (tid < W) ? fkey(v) : 0xFFFFFFFFu;
    unsigned kmn = __reduce_min_sync(FULL, key);
    unsigned kmx = __reduce_max_sync(FULL, (tid < W) ? key : 0u);
    if (lane == 0) { smn[wid] = kmn; smx[wid] = kmx; }
    __syncthreads();                                   // B1: partials + mtm zero visible

    // Every thread finishes the reduction locally (broadcast LDS, no 2nd barrier).
    unsigned a = smn[0], b = smx[0];
    #pragma unroll
    for (int w = 1; w < NWARP; w++) {
        a = min(a, smn[w]);
        b = max(b, smx[w]);
    }
    const float bmn = funkey(a);
    const float bmx = funkey(b);

    // Scale into [-1,1] (same op order as reference) and bucketize against
    // compile-time-constant boundaries (FSETP-imm chain, no memory).
    if (tid < W) {
        float denom = bmx - bmn + 1e-6f;
        float t = (v - bmn) / denom;
        float xsc = t * 2.0f + (-1.0f);
        int cnt = 0;
        #pragma unroll
        for (int k = 1; k < BINS; k++) {
            float bk = (float)(-1.0 + (2.0 * (double)k) / 50.0);  // constant-folded
            cnt += (bk < xsc) ? 1 : 0;
        }
        bins[tid] = cnt;
    }
    __syncthreads();                                   // B2: bins visible

    // Transition histogram.
    if (tid < W - 1) {
        atomicAdd(&mtm[bins[tid] * MPAD + bins[tid + 1]], 1.0f);
    }
    // Contiguous layout: lane owns columns t2 = 4*lane .. 4*lane+3 (one LDS.128).
    const int4 c = reinterpret_cast<const int4*>(bins)[lane];
    __syncthreads();                                   // B3: histogram complete

    // Per bin-row b1: ballots give destination rows AND the row sum
    // (rowsum(b1) = #{t in 0..126 : bins[t]==b1}; t=127 never a source —
    // lane 31's c.w covers t=127, masked out of the count).
    float* o = out + (size_t)s * W * W;
    for (int b1 = wid; b1 < BINS; b1 += NWARP) {
        unsigned m0 = __ballot_sync(FULL, c.x == b1);
        unsigned m1 = __ballot_sync(FULL, c.y == b1);
        unsigned m2 = __ballot_sync(FULL, c.z == b1);
        unsigned m3 = __ballot_sync(FULL, c.w == b1);
        if ((m0 | m1 | m2 | m3) == 0u) continue;

        int rowsum = __popc(m0) + __popc(m1) + __popc(m2) + __popc(m3 & 0x7FFFFFFFu);
        float rinv = (rowsum == 0) ? 1.0f : (1.0f / (float)rowsum);

        const float* row = &mtm[b1 * MPAD];
        float4 val;
        val.x = row[c.x] * rinv;
        val.y = row[c.y] * rinv;
        val.z = row[c.z] * rinv;
        val.w = row[c.w] * rinv;

        // Destinations t1 = 4*idx + j; one streaming STG.128 per row per lane.
        while (m0) {
            int t1 = 4 * (__ffs(m0) - 1); m0 &= m0 - 1;
            __stcs(reinterpret_cast<float4*>(o + t1 * W) + lane, val);
        }
        while (m1) {
            int t1 = 4 * (__ffs(m1) - 1) + 1; m1 &= m1 - 1;
            __stcs(reinterpret_cast<float4*>(o + t1 * W) + lane, val);
        }
        while (m2) {
            int t1 = 4 * (__ffs(m2) - 1) + 2; m2 &= m2 - 1;
            __stcs(reinterpret_cast<float4*>(o + t1 * W) + lane, val);
        }
        while (m3) {
            int t1 = 4 * (__ffs(m3) - 1) + 3; m3 &= m3 - 1;
            __stcs(reinterpret_cast<float4*>(o + t1 * W) + lane, val);
        }
    }
}

extern "C" void kernel_launch(void* const* d_in, const int* in_sizes, int n_in,
                              void* d_out, int out_size) {
    const float* X = (const float*)d_in[0];
    float* out = (float*)d_out;
    int S = in_sizes[0] / W;   // 256*6 = 1536 series (grid == S exactly)
    mtf_kernel<<<S, THREADS>>>(X, out, S);
}

// round 17
// speedup vs baseline: 1.0015x; 1.0015x over previous
#include <cuda_runtime.h>
#include <cuda_bf16.h>
#include <cstdint>
#include <float.h>

#define W 128
#define BINS 50
#define MPAD 64              // row stride; row[lane+32] stays in-bounds for all rows
#define THREADS 256
#define NWARP (THREADS / 32)
#define FULL 0xFFFFFFFFu

// Order-preserving float->uint map: monotone for all finite floats.
__device__ __forceinline__ unsigned fkey(float f) {
    unsigned b = __float_as_uint(f);
    return b ^ (((int)b >> 31) | 0x80000000u);
}
__device__ __forceinline__ float funkey(unsigned k) {
    unsigned b = k ^ ((~(int)k >> 31) | 0x80000000u);
    return __uint_as_float(b);
}

__global__ __launch_bounds__(THREADS, 8)
void mtf_kernel(const float* __restrict__ X, float* __restrict__ out, int S) {
    __shared__ __align__(16) int bins[W];
    __shared__ __align__(16) float mtm[BINS * MPAD];
    __shared__ unsigned smn[NWARP], smx[NWARP];

    const int s    = blockIdx.x;
    const int tid  = threadIdx.x;
    const int lane = tid & 31;
    const int wid  = tid >> 5;

    const float* x = X + (size_t)s * W;

    // Zero transition counts (vectorized STS.128).
    for (int i = tid; i < BINS * MPAD / 4; i += THREADS) {
        reinterpret_cast<float4*>(mtm)[i] = make_float4(0.f, 0.f, 0.f, 0.f);
    }

    // Load series value (threads 0..127); per-warp min/max via redux on keys.
    float v = 0.0f;
    if (tid < W) v = x[tid];
    unsigned key = (tid < W) ? fkey(v) : 0xFFFFFFFFu;
    unsigned kmn = __reduce_min_sync(FULL, key);
    unsigned kmx = __reduce_max_sync(FULL, (tid < W) ? key : 0u);
    if (lane == 0) { smn[wid] = kmn; smx[wid] = kmx; }
    __syncthreads();                                   // B1

    // Every thread finishes the reduction locally (broadcast LDS).
    unsigned a = smn[0], b = smx[0];
    #pragma unroll
    for (int w = 1; w < NWARP; w++) {
        a = min(a, smn[w]);
        b = max(b, smx[w]);
    }
    const float bmn = funkey(a);
    const float bmx = funkey(b);

    // Scale into [-1,1] (same op order as reference) and bucketize against
    // compile-time-constant boundaries (FSETP-imm chain, no memory).
    if (tid < W) {
        float denom = bmx - bmn + 1e-6f;
        float t = (v - bmn) / denom;
        float xsc = t * 2.0f + (-1.0f);
        int cnt = 0;
        #pragma unroll
        for (int k = 1; k < BINS; k++) {
            float bk = (float)(-1.0 + (2.0 * (double)k) / 50.0);  // constant-folded
            cnt += (bk < xsc) ? 1 : 0;
        }
        bins[tid] = cnt;
    }
    __syncthreads();                                   // B2

    // Transition histogram.
    if (tid < W - 1) {
        atomicAdd(&mtm[bins[tid] * MPAD + bins[tid + 1]], 1.0f);
    }
    // Contiguous layout: lane owns columns t2 = 4*lane .. 4*lane+3 (one LDS.128).
    const int4 c = reinterpret_cast<const int4*>(bins)[lane];
    __syncthreads();                                   // B3

    // Per bin-row b1: ballots give destination rows AND the row sum.
    // Gather via SHFL (permute network) instead of conflicted LDS:
    // lane holds row[lane] and row[lane+32], pre-scaled by 1/rowsum.
    float* o = out + (size_t)s * W * W;
    for (int b1 = wid; b1 < BINS; b1 += NWARP) {
        unsigned m0 = __ballot_sync(FULL, c.x == b1);
        unsigned m1 = __ballot_sync(FULL, c.y == b1);
        unsigned m2 = __ballot_sync(FULL, c.z == b1);
        unsigned m3 = __ballot_sync(FULL, c.w == b1);
        if ((m0 | m1 | m2 | m3) == 0u) continue;

        int rowsum = __popc(m0) + __popc(m1) + __popc(m2) + __popc(m3 & 0x7FFFFFFFu);
        float rinv = (rowsum == 0) ? 1.0f : (1.0f / (float)rowsum);

        const float* row = &mtm[b1 * MPAD];
        float r0 = row[lane] * rinv;          // columns 0..31 (conflict-free LDS)
        float r1 = row[lane + 32] * rinv;     // columns 32..49 (lanes 18..31 unused)

        float4 val;
        {
            float lo, hi;
            lo = __shfl_sync(FULL, r0, c.x & 31); hi = __shfl_sync(FULL, r1, c.x & 31);
            val.x = (c.x < 32) ? lo : hi;
            lo = __shfl_sync(FULL, r0, c.y & 31); hi = __shfl_sync(FULL, r1, c.y & 31);
            val.y = (c.y < 32) ? lo : hi;
            lo = __shfl_sync(FULL, r0, c.z & 31); hi = __shfl_sync(FULL, r1, c.z & 31);
            val.z = (c.z < 32) ? lo : hi;
            lo = __shfl_sync(FULL, r0, c.w & 31); hi = __shfl_sync(FULL, r1, c.w & 31);
            val.w = (c.w < 32) ? lo : hi;
        }

        // Destinations t1 = 4*idx + j; one streaming STG.128 per row per lane.
        while (m0) {
            int t1 = 4 * (__ffs(m0) - 1); m0 &= m0 - 1;
            __stcs(reinterpret_cast<float4*>(o + t1 * W) + lane, val);
        }
        while (m1) {
            int t1 = 4 * (__ffs(m1) - 1) + 1; m1 &= m1 - 1;
            __stcs(reinterpret_cast<float4*>(o + t1 * W) + lane, val);
        }
        while (m2) {
            int t1 = 4 * (__ffs(m2) - 1) + 2; m2 &= m2 - 1;
            __stcs(reinterpret_cast<float4*>(o + t1 * W) + lane, val);
        }
        while (m3) {
            int t1 = 4 * (__ffs(m3) - 1) + 3; m3 &= m3 - 1;
            __stcs(reinterpret_cast<float4*>(o + t1 * W) + lane, val);
        }
    }
}

extern "C" void kernel_launch(void* const* d_in, const int* in_sizes, int n_in,
                              void* d_out, int out_size) {
    const float* X = (const float*)d_in[0];
    float* out = (float*)d_out;
    int S = in_sizes[0] / W;   // 256*6 = 1536 series (grid == S exactly)
    mtf_kernel<<<S, THREADS>>>(X, out, S);
}